// round 1
// baseline (speedup 1.0000x reference)
#include <cuda_runtime.h>
#include <cuda_bf16.h>

#define NSPECIES 4
#define FDIM 128
#define HDIM 64

// ---- dynamic smem float-offset layout ----
#define OFF_W1 0
#define OFF_W2 (NSPECIES*FDIM*HDIM)                  // 32768
#define OFF_W3 (OFF_W2 + NSPECIES*HDIM*HDIM)        // 49152
#define OFF_B1 (OFF_W3 + NSPECIES*HDIM)             // 49408
#define OFF_B2 (OFF_B1 + NSPECIES*HDIM)             // 49664
#define OFF_B3 (OFF_B2 + NSPECIES*HDIM)             // 49920
#define SMEM_FLOATS (OFF_B3 + NSPECIES)             // 49924 -> 199696 bytes

__device__ int g_species_is64;

// The reference declares species as int64, but JAX without x64 silently
// produces int32. Detect at runtime: if the buffer is int32 with values in
// [0,3], an int64 reinterpretation of consecutive pairs will (with prob
// 1 - 4^-128) produce a value > 3. Reads only 1 KB, in-bounds either way.
__global__ void detect_species_dtype_kernel(const long long* __restrict__ sp) {
    if (threadIdx.x == 0 && blockIdx.x == 0) {
        int ok = 1;
        #pragma unroll 1
        for (int i = 0; i < 128; i++) {
            long long v = sp[i];
            if (v < 0 || v > 3) { ok = 0; break; }
        }
        g_species_is64 = ok;
    }
}

__device__ __forceinline__ float fast_tanh(float x) {
    // tanh(x) = 1 - 2/(exp(2x)+1). Stable at both infinities:
    //   exp->inf : 1 - 0 = 1 ;  exp->0 : 1 - 2 = -1.
    float e = __expf(2.0f * x);
    return 1.0f - __fdividef(2.0f, e + 1.0f);
}

extern __shared__ float smem[];

__global__ void __launch_bounds__(384, 1)
mlp_dispatch_kernel(const float* __restrict__ features,
                    const void*  __restrict__ species,
                    const float* __restrict__ W1, const float* __restrict__ b1,
                    const float* __restrict__ W2, const float* __restrict__ b2,
                    const float* __restrict__ W3, const float* __restrict__ b3,
                    float* __restrict__ out, int n)
{
    // ---- cooperative weight staging (all 4 species resident in SMEM) ----
    {
        const int tid = threadIdx.x;
        float4* s4 = reinterpret_cast<float4*>(smem);
        const float4* g;

        g = reinterpret_cast<const float4*>(W1);
        for (int i = tid; i < (NSPECIES*FDIM*HDIM)/4; i += blockDim.x) s4[OFF_W1/4 + i] = g[i];
        g = reinterpret_cast<const float4*>(W2);
        for (int i = tid; i < (NSPECIES*HDIM*HDIM)/4; i += blockDim.x) s4[OFF_W2/4 + i] = g[i];
        g = reinterpret_cast<const float4*>(W3);
        for (int i = tid; i < (NSPECIES*HDIM)/4; i += blockDim.x)      s4[OFF_W3/4 + i] = g[i];
        g = reinterpret_cast<const float4*>(b1);
        for (int i = tid; i < (NSPECIES*HDIM)/4; i += blockDim.x)      s4[OFF_B1/4 + i] = g[i];
        g = reinterpret_cast<const float4*>(b2);
        for (int i = tid; i < (NSPECIES*HDIM)/4; i += blockDim.x)      s4[OFF_B2/4 + i] = g[i];
        if (tid < NSPECIES) smem[OFF_B3 + tid] = b3[tid];
    }
    __syncthreads();

    const int is64 = g_species_is64;
    const long long* sp64 = reinterpret_cast<const long long*>(species);
    const int*       sp32 = reinterpret_cast<const int*>(species);

    const int stride = gridDim.x * blockDim.x;
    for (int atom = blockIdx.x * blockDim.x + threadIdx.x; atom < n; atom += stride) {
        const int s = is64 ? (int)sp64[atom] : sp32[atom];

        const float4* frow   = reinterpret_cast<const float4*>(features + (size_t)atom * FDIM);
        const float*  w1base = smem + OFF_W1 + s * (FDIM*HDIM);
        const float*  b1base = smem + OFF_B1 + s * HDIM;

        // ---- layer 1: h = features[atom] @ W1[s] + b1[s] ----
        float h[HDIM];
        #pragma unroll
        for (int j = 0; j < HDIM; j++) h[j] = b1base[j];

        #pragma unroll 2
        for (int k4 = 0; k4 < FDIM/4; k4++) {
            const float4 f = frow[k4];
            const float fc[4] = {f.x, f.y, f.z, f.w};
            #pragma unroll
            for (int c = 0; c < 4; c++) {
                const float  fv = fc[c];
                const float4* w = reinterpret_cast<const float4*>(w1base + (k4*4 + c) * HDIM);
                #pragma unroll
                for (int j4 = 0; j4 < HDIM/4; j4++) {
                    const float4 wv = w[j4];
                    h[4*j4+0] += fv * wv.x;
                    h[4*j4+1] += fv * wv.y;
                    h[4*j4+2] += fv * wv.z;
                    h[4*j4+3] += fv * wv.w;
                }
            }
        }

        #pragma unroll
        for (int j = 0; j < HDIM; j++) h[j] = fast_tanh(h[j]);

        // ---- layer 2 + layer 3, j-blocked (16 outputs per block) ----
        const float* w2base = smem + OFF_W2 + s * (HDIM*HDIM);
        const float* w3base = smem + OFF_W3 + s * HDIM;
        const float* b2base = smem + OFF_B2 + s * HDIM;
        float e = smem[OFF_B3 + s];

        #pragma unroll 1
        for (int jb = 0; jb < HDIM/16; jb++) {
            float acc[16];
            #pragma unroll
            for (int i = 0; i < 16; i++) acc[i] = b2base[jb*16 + i];

            #pragma unroll
            for (int k = 0; k < HDIM; k++) {
                const float tk = h[k];
                const float4* w = reinterpret_cast<const float4*>(w2base + k*HDIM + jb*16);
                #pragma unroll
                for (int i4 = 0; i4 < 4; i4++) {
                    const float4 wv = w[i4];
                    acc[4*i4+0] += tk * wv.x;
                    acc[4*i4+1] += tk * wv.y;
                    acc[4*i4+2] += tk * wv.z;
                    acc[4*i4+3] += tk * wv.w;
                }
            }
            #pragma unroll
            for (int i = 0; i < 16; i++)
                e += fast_tanh(acc[i]) * w3base[jb*16 + i];
        }

        out[atom] = e;
    }
}

extern "C" void kernel_launch(void* const* d_in, const int* in_sizes, int n_in,
                              void* d_out, int out_size)
{
    const float* feats   = (const float*)d_in[0];
    const void*  species = d_in[1];
    const float* W1 = (const float*)d_in[2];
    const float* b1 = (const float*)d_in[3];
    const float* W2 = (const float*)d_in[4];
    const float* b2 = (const float*)d_in[5];
    const float* W3 = (const float*)d_in[6];
    const float* b3 = (const float*)d_in[7];
    float* out = (float*)d_out;
    const int n = out_size;

    detect_species_dtype_kernel<<<1, 32>>>((const long long*)species);

    const size_t smem_bytes = SMEM_FLOATS * sizeof(float);
    cudaFuncSetAttribute(mlp_dispatch_kernel,
                         cudaFuncAttributeMaxDynamicSharedMemorySize,
                         (int)smem_bytes);

    int dev = 0;
    cudaGetDevice(&dev);
    int nsm = 148;
    cudaDeviceGetAttribute(&nsm, cudaDevAttrMultiProcessorCount, dev);

    mlp_dispatch_kernel<<<nsm, 384, smem_bytes>>>(
        feats, species, W1, b1, W2, b2, W3, b3, out, n);
}

// round 2
// speedup vs baseline: 3.4547x; 3.4547x over previous
#include <cuda_runtime.h>

typedef unsigned long long ull;

#define NSPECIES 4
#define FDIM 128
#define HDIM 64
#define MAXN 2000000

// ---------------- device scratch (no allocations allowed) ----------------
__device__ int g_is64;
__device__ int g_counts[NSPECIES];
__device__ int g_offsets[NSPECIES + 1];
__device__ int g_cursor[NSPECIES];
__device__ int g_sorted[MAXN];

// ---------------- packed f32x2 helpers ----------------
__device__ __forceinline__ ull pk(float lo, float hi) {
    ull r;
    asm("mov.b64 %0, {%1, %2};" : "=l"(r)
        : "r"(__float_as_uint(lo)), "r"(__float_as_uint(hi)));
    return r;
}
__device__ __forceinline__ void upk(ull v, float& lo, float& hi) {
    unsigned a, b;
    asm("mov.b64 {%0, %1}, %2;" : "=r"(a), "=r"(b) : "l"(v));
    lo = __uint_as_float(a);
    hi = __uint_as_float(b);
}
__device__ __forceinline__ ull ffma2(ull a, ull b, ull c) {
    ull d;
    asm("fma.rn.f32x2 %0, %1, %2, %3;" : "=l"(d) : "l"(a), "l"(b), "l"(c));
    return d;
}

__device__ __forceinline__ float fast_tanh(float x) {
    // tanh(x) = 1 - 2/(exp(2x)+1); stable at +/-inf.
    float e = __expf(2.0f * x);
    return 1.0f - __fdividef(2.0f, e + 1.0f);
}
__device__ __forceinline__ ull tanh2(ull v) {
    float a, b;
    upk(v, a, b);
    return pk(fast_tanh(a), fast_tanh(b));
}

// ---------------- species dtype detection + reset ----------------
// Reference declares int64, JAX default emits int32. If buffer is int32 with
// values in [0,3], int64 reinterpretation of pairs is >3 or <0 with prob
// 1 - 4^-128 over 128 samples.
__global__ void detect_kernel(const long long* __restrict__ sp, int n) {
    if (threadIdx.x == 0 && blockIdx.x == 0) {
        int ok = 1;
        int m = (n / 2 < 128) ? n / 2 : 128;
        #pragma unroll 1
        for (int i = 0; i < m; i++) {
            long long v = sp[i];
            if (v < 0 || v > 3) { ok = 0; break; }
        }
        g_is64 = ok;
        #pragma unroll
        for (int s = 0; s < NSPECIES; s++) { g_counts[s] = 0; g_cursor[s] = 0; }
    }
}

__device__ __forceinline__ int load_species(const void* sp, int i, int is64) {
    return is64 ? (int)((const long long*)sp)[i] : ((const int*)sp)[i];
}

__global__ void hist_kernel(const void* __restrict__ sp, int n) {
    __shared__ int hs[NSPECIES];
    if (threadIdx.x < NSPECIES) hs[threadIdx.x] = 0;
    __syncthreads();
    const int is64 = g_is64;
    const int stride = gridDim.x * blockDim.x;
    for (int i = blockIdx.x * blockDim.x + threadIdx.x; i < n; i += stride)
        atomicAdd(&hs[load_species(sp, i, is64)], 1);
    __syncthreads();
    if (threadIdx.x < NSPECIES) atomicAdd(&g_counts[threadIdx.x], hs[threadIdx.x]);
}

__global__ void offsets_kernel() {
    if (threadIdx.x == 0 && blockIdx.x == 0) {
        int acc = 0;
        #pragma unroll
        for (int s = 0; s < NSPECIES; s++) {
            g_offsets[s] = acc;
            g_cursor[s] = acc;
            acc += g_counts[s];
        }
        g_offsets[NSPECIES] = acc;
    }
}

// Warp-aggregated scatter: one global atomic per (warp, species-group).
__global__ void scatter_kernel(const void* __restrict__ sp, int n) {
    const int is64 = g_is64;
    const int stride = gridDim.x * blockDim.x;
    const int lane = threadIdx.x & 31;
    for (int i = blockIdx.x * blockDim.x + threadIdx.x; i < n; i += stride) {
        int s = load_species(sp, i, is64);
        unsigned act = __activemask();
        unsigned peers = __match_any_sync(act, s);
        int leader = __ffs(peers) - 1;
        int cnt = __popc(peers);
        int base = 0;
        if (lane == leader) base = atomicAdd(&g_cursor[s], cnt);
        base = __shfl_sync(peers, base, leader);
        int pos = base + __popc(peers & ((1u << lane) - 1u));
        g_sorted[pos] = i;
    }
}

// ---------------- main MLP kernel ----------------
// SMEM float layout: duplicated (w,w) weight pairs.
#define OFF_W1D 0                        // 128*64*2 = 16384
#define OFF_W2T (OFF_W1D + 16384)        // W2 TRANSPOSED [j][k], dup: 64*64*2 = 8192
#define OFF_B1D (OFF_W2T + 8192)         // 128
#define OFF_B2D (OFF_B1D + 128)          // 128
#define OFF_W3D (OFF_B2D + 128)          // 128
#define OFF_B3S (OFF_W3D + 128)          // 4
#define SMEM_FLOATS (OFF_B3S + 4)        // 24968 floats = 99872 B

extern __shared__ float sm[];

__global__ void __launch_bounds__(256, 1)
mlp2_kernel(const float* __restrict__ feats,
            const float* __restrict__ W1, const float* __restrict__ b1,
            const float* __restrict__ W2, const float* __restrict__ b2,
            const float* __restrict__ W3, const float* __restrict__ b3,
            float* __restrict__ out)
{
    const int s = blockIdx.x & 3;           // species for this CTA
    const int cta_in_s = blockIdx.x >> 2;   // CTA index within species group
    const int ctas_per_s = gridDim.x >> 2;

    // ---- stage this species' weights, duplicated (w,w) ----
    {
        const int tid = threadIdx.x;
        const float* W1s = W1 + s * (FDIM * HDIM);
        for (int i = tid; i < FDIM * HDIM; i += blockDim.x) {
            float w = W1s[i];
            sm[OFF_W1D + 2 * i] = w;
            sm[OFF_W1D + 2 * i + 1] = w;
        }
        const float* W2s = W2 + s * (HDIM * HDIM);
        for (int i = tid; i < HDIM * HDIM; i += blockDim.x) {
            int k = i / HDIM, j = i % HDIM;     // global W2 is [k][j]
            float w = W2s[i];
            sm[OFF_W2T + 2 * (j * HDIM + k)] = w;      // store transposed [j][k]
            sm[OFF_W2T + 2 * (j * HDIM + k) + 1] = w;
        }
        if (tid < HDIM) {
            float v1 = b1[s * HDIM + tid];
            sm[OFF_B1D + 2 * tid] = v1; sm[OFF_B1D + 2 * tid + 1] = v1;
            float v2 = b2[s * HDIM + tid];
            sm[OFF_B2D + 2 * tid] = v2; sm[OFF_B2D + 2 * tid + 1] = v2;
            float v3 = W3[s * HDIM + tid];
            sm[OFF_W3D + 2 * tid] = v3; sm[OFF_W3D + 2 * tid + 1] = v3;
        }
        if (tid == 0) sm[OFF_B3S] = b3[s];
    }
    __syncthreads();

    const int beg = g_offsets[s];
    const int end = g_offsets[s + 1];
    const int npairs = (end - beg + 1) >> 1;
    const float b3v = sm[OFF_B3S];

    const ull* b1p = (const ull*)(sm + OFF_B1D);
    const ull* b2p = (const ull*)(sm + OFF_B2D);
    const ull* w3p = (const ull*)(sm + OFF_W3D);

    const int pstride = ctas_per_s * blockDim.x;
    for (int p = cta_in_s * blockDim.x + threadIdx.x; p < npairs; p += pstride) {
        const int i0 = beg + 2 * p;
        int i1 = i0 + 1;
        const bool dup = (i1 >= end);
        if (dup) i1 = i0;
        const int a0 = g_sorted[i0];
        const int a1 = g_sorted[i1];

        const float4* f0 = (const float4*)(feats + (size_t)a0 * FDIM);
        const float4* f1 = (const float4*)(feats + (size_t)a1 * FDIM);

        // ---- layer 1: h2[j] = b1 + sum_k f[k]*W1[k][j], both atoms packed ----
        ull h2[HDIM];
        #pragma unroll
        for (int j = 0; j < HDIM; j++) h2[j] = b1p[j];

        #pragma unroll 1
        for (int k4 = 0; k4 < FDIM / 4; k4++) {
            const float4 x0 = f0[k4];
            const float4 x1 = f1[k4];
            ull fp[4];
            fp[0] = pk(x0.x, x1.x);
            fp[1] = pk(x0.y, x1.y);
            fp[2] = pk(x0.z, x1.z);
            fp[3] = pk(x0.w, x1.w);
            const ulonglong2* wp = (const ulonglong2*)(sm + OFF_W1D) + (size_t)k4 * 4 * 32;
            #pragma unroll
            for (int c = 0; c < 4; c++) {
                #pragma unroll
                for (int j2 = 0; j2 < 32; j2++) {
                    ulonglong2 w = wp[c * 32 + j2];
                    h2[2 * j2]     = ffma2(fp[c], w.x, h2[2 * j2]);
                    h2[2 * j2 + 1] = ffma2(fp[c], w.y, h2[2 * j2 + 1]);
                }
            }
        }

        #pragma unroll
        for (int j = 0; j < HDIM; j++) h2[j] = tanh2(h2[j]);

        // ---- layer 2 + 3: two output columns per iteration ----
        ull e2 = pk(b3v, b3v);
        #pragma unroll 1
        for (int j2 = 0; j2 < 32; j2++) {
            ull acc0 = b2p[2 * j2];
            ull acc1 = b2p[2 * j2 + 1];
            const ulonglong2* wp0 = (const ulonglong2*)(sm + OFF_W2T) + (size_t)(2 * j2) * 32;
            const ulonglong2* wp1 = wp0 + 32;
            #pragma unroll
            for (int k2 = 0; k2 < 32; k2++) {
                ulonglong2 w0 = wp0[k2];
                ulonglong2 w1 = wp1[k2];
                acc0 = ffma2(h2[2 * k2],     w0.x, acc0);
                acc0 = ffma2(h2[2 * k2 + 1], w0.y, acc0);
                acc1 = ffma2(h2[2 * k2],     w1.x, acc1);
                acc1 = ffma2(h2[2 * k2 + 1], w1.y, acc1);
            }
            e2 = ffma2(tanh2(acc0), w3p[2 * j2], e2);
            e2 = ffma2(tanh2(acc1), w3p[2 * j2 + 1], e2);
        }

        float e0, e1;
        upk(e2, e0, e1);
        out[a0] = e0;
        if (!dup) out[a1] = e1;
    }
}

// ---------------- launch ----------------
extern "C" void kernel_launch(void* const* d_in, const int* in_sizes, int n_in,
                              void* d_out, int out_size)
{
    const float* feats   = (const float*)d_in[0];
    const void*  species = d_in[1];
    const float* W1 = (const float*)d_in[2];
    const float* b1 = (const float*)d_in[3];
    const float* W2 = (const float*)d_in[4];
    const float* b2 = (const float*)d_in[5];
    const float* W3 = (const float*)d_in[6];
    const float* b3 = (const float*)d_in[7];
    float* out = (float*)d_out;
    const int n = out_size;

    int dev = 0;
    cudaGetDevice(&dev);
    int nsm = 148;
    cudaDeviceGetAttribute(&nsm, cudaDevAttrMultiProcessorCount, dev);

    detect_kernel<<<1, 32>>>((const long long*)species, n);
    hist_kernel<<<nsm, 256>>>(species, n);
    offsets_kernel<<<1, 32>>>();
    scatter_kernel<<<nsm, 256>>>(species, n);

    const size_t smem_bytes = SMEM_FLOATS * sizeof(float);
    cudaFuncSetAttribute(mlp2_kernel,
                         cudaFuncAttributeMaxDynamicSharedMemorySize,
                         (int)smem_bytes);
    int grid = nsm & ~3;   // multiple of 4: equal CTAs per species
    mlp2_kernel<<<grid, 256, smem_bytes>>>(feats, W1, b1, W2, b2, W3, b3, out);
}